// round 11
// baseline (speedup 1.0000x reference)
#include <cuda_runtime.h>

// ARIMA(16,1,16), S = 2^20 — recurrence-free formulation.
// err[t] = sum_{i=0..80} hh[i] * s[t+1-i], where hh = g (x) q:
//   q = 18-tap FIR mapping raw series -> x (diff + AR),
//   g = impulse response of the MA recurrence 1/(1 + sum c_j z^-j),
//       truncated at 64 taps (|g[k]| ~ 0.9^k -> rel err ~2e-5).
// One kernel, 128 blocks x 256 threads. Per block: stage series tile in
// padded smem; lane 0 generates g (packed DF2-T, hidden under tile load);
// 81 threads build hh; then pure packed-f32x2 81-tap conv, 8 outputs/thread
// per task, 4 tasks/thread. Outputs t<80 masked from conv and computed
// exactly in parallel. Last-block-done reduction in-kernel.

#define S_LEN 1048576
#define NWARP 1024
#define WPB   8
#define NBLK  (NWARP / WPB)        // 128
#define OPW   1024                 // outputs per warp
#define OPB   (OPW * WPB)          // 8192
#define SS_N  8274                 // staged series floats per block
#define SS_P  9312                 // padded size, f(r) = r + (r>>3)
#define F(r)  ((r) + ((r) >> 3))

typedef unsigned long long ull;

__device__ float    g_partial[NWARP];
__device__ unsigned g_cnt;          // zero-init; reset by last block

__device__ __forceinline__ ull pack2(float lo, float hi) {
    ull r; asm("mov.b64 %0, {%1,%2};" : "=l"(r) : "f"(lo), "f"(hi)); return r;
}
__device__ __forceinline__ void unpack2(ull v, float& lo, float& hi) {
    asm("mov.b64 {%0,%1}, %2;" : "=f"(lo), "=f"(hi) : "l"(v));
}
__device__ __forceinline__ ull fma2(ull a, ull b, ull c) {
    ull r; asm("fma.rn.f32x2 %0, %1, %2, %3;" : "=l"(r)
               : "l"(a), "l"(b), "l"(c));
    return r;
}

// 2 recurrence steps emitting the two outputs (used only to generate g).
__device__ __forceinline__ void step2g(ull* P, const ull* PA, const ull* PB,
                                       float nc0, float x0, float x1,
                                       float& e0, float& e1) {
    float d0, d1;
    unpack2(P[0], d0, d1);
    e0 = x0 + d0;
    e1 = fmaf(nc0, e0, x1 + d1);
    ull E = pack2(e0, e0), Fv = pack2(e1, e1);
#pragma unroll
    for (int k = 0; k < 8; ++k)
        P[k] = fma2(PB[k], Fv, fma2(PA[k], E, P[k + 1]));
}

__global__ void __launch_bounds__(256) fused_kernel(const float* __restrict__ s,
                                                    const float* __restrict__ w_ar,
                                                    const float* __restrict__ w_ma,
                                                    float* __restrict__ out) {
    __shared__ __align__(16) float ss[SS_P];
    __shared__ float    garr[64];
    __shared__ ull      hh2s[81];
    __shared__ float    xs[80];
    __shared__ double   sm[WPB];
    __shared__ unsigned s_done;

    const int tid = threadIdx.x;
    const int l   = tid & 31;
    const int wid = tid >> 5;
    const int bid = blockIdx.x;
    const int g   = bid * WPB + wid;
    const int bb  = bid * OPB;         // first output of this block
    const int SSB = bb - 80;           // ss[i] = s[SSB + i]

    // ---- Phase 0: warp 0 lane 0 generates g; warps 1..7 stage the tile ----
    if (wid == 0) {
        if (l == 0) {
            float nc[16];
#pragma unroll
            for (int j = 0; j < 16; ++j) nc[j] = -w_ma[15 - j];
            ull PA[8], PB[8];
#pragma unroll
            for (int k = 0; k < 8; ++k) {
                PA[k] = pack2(nc[2 * k + 1],
                              (2 * k + 2 < 16) ? nc[2 * k + 2] : 0.f);
                PB[k] = pack2(nc[2 * k], nc[2 * k + 1]);
            }
            ull P[9];
#pragma unroll
            for (int k = 0; k < 9; ++k) P[k] = 0ULL;
            for (int it = 0; it < 32; ++it) {
                float e0, e1;
                step2g(P, PA, PB, nc[0], (it == 0) ? 1.f : 0.f, 0.f, e0, e1);
                garr[2 * it]     = e0;
                garr[2 * it + 1] = e1;
            }
        }
    } else {
        const int i0 = tid - 32;       // 224 loader threads
        if (bid == 0 || bid == NBLK - 1) {
            for (int i = i0; i < SS_N; i += 224) {
                int p = SSB + i;
                float v = 0.f;
                if (p >= 0) { if (p > S_LEN) p = S_LEN; v = s[p]; }
                ss[F(i)] = v;
            }
        } else {
            const float4* src = (const float4*)(s + SSB);   // SSB % 16 == 0
            for (int i = i0; i < 2069; i += 224) {
                float4 t4 = src[i];
                int fb = F(4 * i);     // quad never crosses a pad boundary
                ss[fb] = t4.x; ss[fb + 1] = t4.y;
                ss[fb + 2] = t4.z; ss[fb + 3] = t4.w;
            }
        }
    }
    __syncthreads();

    // ---- Phase 1: hh = g (x) q (81 taps); block 0 also builds x~[0..79] ----
    if (tid < 81) {
        float q[18];
        q[0] = w_ar[0];
#pragma unroll
        for (int m = 1; m < 16; ++m) q[m] = w_ar[m] - w_ar[m - 1];
        q[16] = -1.f - w_ar[15];
        q[17] = 1.f;
        float h = 0.f;
#pragma unroll
        for (int m = 0; m < 18; ++m) {
            int k = tid - 17 + m;      // hh[i] = sum_k g[k] q[k+17-i]
            if (k >= 0 && k < 64) h = fmaf(q[m], garr[k], h);
        }
        hh2s[tid] = pack2(h, h);
    }
    if (bid == 0 && tid >= 160 && tid < 240) {
        const int u = tid - 160;       // 0..79; s[p] = ss[p + 80] here
        float v;
        if (u <= 16) {                 // x~ = y_u + sum_{j<=u} c_j y_{u-j}
            v = ss[F(u + 81)] - ss[F(u + 80)];
            for (int j = 1; j <= u; ++j)
                v = fmaf(w_ma[16 - j],
                         ss[F(u - j + 81)] - ss[F(u - j + 80)], v);
        } else {                       // plain q-conv
            float q[18];
            q[0] = w_ar[0];
#pragma unroll
            for (int m = 1; m < 16; ++m) q[m] = w_ar[m] - w_ar[m - 1];
            q[16] = -1.f - w_ar[15];
            q[17] = 1.f;
            v = 0.f;
#pragma unroll
            for (int m = 0; m < 18; ++m)
                v = fmaf(q[m], ss[F(u + 64 + m)], v);
        }
        xs[u] = v;
    }
    __syncthreads();

    // ---- Phase 2a: block 0 warp 0 — exact err for t in [0, 80) ----
    float accE = 0.f;
    if (bid == 0 && wid == 0) {
#pragma unroll
        for (int rr = 0; rr < 3; ++rr) {
            int t = l + 32 * rr;
            if (t < 80) {
                float e = 0.f;
                int kmax = t < 63 ? t : 63;
                for (int k = 0; k <= kmax; ++k)
                    e = fmaf(garr[k], xs[t - k], e);
                accE = fmaf(e, e, accE);
            }
        }
    }

    // ---- Phase 2b: main 81-tap packed conv, 8 outputs x 4 tasks/thread ----
    ull acc2 = 0ULL;
#pragma unroll 1
    for (int tau = 0; tau < 4; ++tau) {
        const int tloc = wid * OPW + tau * 256 + 8 * l;  // first output (local)
        const int b = tloc + 1;        // ss idx of tap i=80's pair base
        float u0 = ss[F(b)],     u1 = ss[F(b + 1)], u2 = ss[F(b + 2)],
              u3 = ss[F(b + 3)], u4 = ss[F(b + 4)], u5 = ss[F(b + 5)],
              u6 = ss[F(b + 6)], u7 = ss[F(b + 7)];
        ull Q0 = pack2(u0, u1), Q1 = pack2(u2, u3);
        ull Q2 = pack2(u4, u5), Q3 = pack2(u6, u7);
        float up = u7;
        ull E0 = 0ULL, E1 = 0ULL, E2 = 0ULL, E3 = 0ULL;
#pragma unroll
        for (int j = 0; j < 81; ++j) {          // tap i = 80 - j, s ascending
            ull h2 = hh2s[80 - j];
            E0 = fma2(h2, Q0, E0);
            E1 = fma2(h2, Q1, E1);
            E2 = fma2(h2, Q2, E2);
            E3 = fma2(h2, Q3, E3);
            float un = ss[F(b + 8 + j)];
            Q0 = Q1; Q1 = Q2; Q2 = Q3;
            Q3 = pack2(up, un);
            up = un;
        }
        const bool skip = (g == 0) & (tau == 0) & (l < 10);  // t < 80 handled exactly
        if (!skip) {
            acc2 = fma2(E0, E0, acc2);
            acc2 = fma2(E1, E1, acc2);
            acc2 = fma2(E2, E2, acc2);
            acc2 = fma2(E3, E3, acc2);
        }
    }

    float alo, ahi;
    unpack2(acc2, alo, ahi);
    float acc = alo + ahi + accE;
#pragma unroll
    for (int off = 16; off; off >>= 1)
        acc += __shfl_down_sync(0xffffffffu, acc, off);
    if (l == 0) g_partial[g] = acc;

    // ---- last-block-done final reduction ----
    __threadfence();
    __syncthreads();
    if (tid == 0) {
        unsigned old = atomicAdd(&g_cnt, 1u);
        s_done = (old == gridDim.x - 1) ? 1u : 0u;
    }
    __syncthreads();
    if (s_done) {
        double v = 0.0;
#pragma unroll
        for (int k = 0; k < NWARP / 256; ++k)
            v += (double)((volatile float*)g_partial)[tid + 256 * k];
#pragma unroll
        for (int off = 16; off; off >>= 1)
            v += __shfl_down_sync(0xffffffffu, v, off);
        if (l == 0) sm[wid] = v;
        __syncthreads();
        if (tid == 0) {
            double w = 0.0;
#pragma unroll
            for (int k = 0; k < WPB; ++k) w += sm[k];
            out[0] = (float)(w * (1.0 / (double)S_LEN));
            g_cnt = 0;                 // reset for next graph replay
        }
    }
}

extern "C" void kernel_launch(void* const* d_in, const int* in_sizes, int n_in,
                              void* d_out, int out_size) {
    const float* series = (const float*)d_in[0];
    const float* w_ar   = (const float*)d_in[1];
    const float* w_ma   = (const float*)d_in[2];
    float* out = (float*)d_out;
    fused_kernel<<<NBLK, 256>>>(series, w_ar, w_ma, out);
}

// round 12
// speedup vs baseline: 1.1863x; 1.1863x over previous
#include <cuda_runtime.h>

// ARIMA(16,1,16), S = 2^20 — recurrence-free: err[t] = sum_{i<=80} hh[i]*s[t+1-i],
// hh = g (x) q (g = 64-tap impulse response of the MA recurrence, q = 18-tap
// diff+AR FIR). One kernel, 128 blocks x 256 threads, single wave.
// Per block: build packed-pair smem array ps[i] = (s[i], s[i+1]) (64-bit,
// bank-pad u+(u>>4)); lane0 generates g meanwhile. Conv: each lane computes
// 32 outputs = 16 f32x2 pairs via a rolling 32-ull register window with
// static modular indexing (no shifts, no packs): per tap 16 fma2 + 1 LDS.64
// + 1 broadcast LDS.64. Outputs t<96 masked and computed exactly.
// Last-block-done reduction in-kernel.

#define S_LEN 1048576
#define NWARP 1024
#define WPB   8
#define NBLK  (NWARP / WPB)        // 128
#define OPB   8192                 // outputs per block
#define NPS   8276                 // ps pairs built per block
#define PSALLOC 8800               // padded ull allocation
#define PF(u) ((u) + ((u) >> 4))

typedef unsigned long long ull;

__device__ float    g_partial[NWARP];
__device__ unsigned g_cnt;          // zero-init; reset by last block

__device__ __forceinline__ ull pack2(float lo, float hi) {
    ull r; asm("mov.b64 %0, {%1,%2};" : "=l"(r) : "f"(lo), "f"(hi)); return r;
}
__device__ __forceinline__ void unpack2(ull v, float& lo, float& hi) {
    asm("mov.b64 {%0,%1}, %2;" : "=f"(lo), "=f"(hi) : "l"(v));
}
__device__ __forceinline__ ull fma2(ull a, ull b, ull c) {
    ull r; asm("fma.rn.f32x2 %0, %1, %2, %3;" : "=l"(r)
               : "l"(a), "l"(b), "l"(c));
    return r;
}

// 2 recurrence steps emitting both outputs (only used to generate g).
__device__ __forceinline__ void step2g(ull* P, const ull* PA, const ull* PB,
                                       float nc0, float x0, float x1,
                                       float& e0, float& e1) {
    float d0, d1;
    unpack2(P[0], d0, d1);
    e0 = x0 + d0;
    e1 = fmaf(nc0, e0, x1 + d1);
    ull E = pack2(e0, e0), Fv = pack2(e1, e1);
#pragma unroll
    for (int k = 0; k < 8; ++k)
        P[k] = fma2(PB[k], Fv, fma2(PA[k], E, P[k + 1]));
}

__global__ void __launch_bounds__(256) fused_kernel(const float* __restrict__ s,
                                                    const float* __restrict__ w_ar,
                                                    const float* __restrict__ w_ma,
                                                    float* __restrict__ out) {
    extern __shared__ __align__(16) ull ps[];       // [PSALLOC]
    __shared__ float    garr[64];
    __shared__ ull      hh2s[81];
    __shared__ float    xs[96];
    __shared__ double   sm[WPB];
    __shared__ unsigned s_done;

    const int tid = threadIdx.x;
    const int l   = tid & 31;
    const int wid = tid >> 5;
    const int bid = blockIdx.x;
    const int gw  = bid * WPB + wid;
    const int bb  = bid * OPB;          // first output of this block
    const int SSB = bb - 80;            // ps[u] = (s[SSB+u], s[SSB+u+1])

    // ---- Phase 0: lane 0 of warp 0 generates g; tid>=32 builds ps ----
    if (wid == 0) {
        if (l == 0) {
            float nc[16];
#pragma unroll
            for (int j = 0; j < 16; ++j) nc[j] = -w_ma[15 - j];
            ull PA[8], PB[8];
#pragma unroll
            for (int k = 0; k < 8; ++k) {
                PA[k] = pack2(nc[2 * k + 1],
                              (2 * k + 2 < 16) ? nc[2 * k + 2] : 0.f);
                PB[k] = pack2(nc[2 * k], nc[2 * k + 1]);
            }
            ull P[9];
#pragma unroll
            for (int k = 0; k < 9; ++k) P[k] = 0ULL;
            for (int it = 0; it < 32; ++it) {
                float e0, e1;
                step2g(P, PA, PB, nc[0], (it == 0) ? 1.f : 0.f, 0.f, e0, e1);
                garr[2 * it]     = e0;
                garr[2 * it + 1] = e1;
            }
        }
    } else {
        const int i0 = tid - 32;        // 224 builder threads
        if (bid == 0 || bid == NBLK - 1) {
            for (int u = i0; u < NPS; u += 224) {
                int p0 = SSB + u, p1 = SSB + u + 1;
                p0 = p0 < 0 ? 0 : (p0 > S_LEN ? S_LEN : p0);
                p1 = p1 < 0 ? 0 : (p1 > S_LEN ? S_LEN : p1);
                ps[PF(u)] = pack2(s[p0], s[p1]);
            }
        } else {
            const float4* src = (const float4*)(s + SSB);   // SSB % 4 == 0
            const float*  sf  = s + SSB;
            for (int i = i0; i < 2069; i += 224) {          // covers u<8276
                float4 a = src[i];
                float  nx = sf[4 * i + 4];
                const int u = 4 * i;
                ps[PF(u)]     = pack2(a.x, a.y);
                ps[PF(u + 1)] = pack2(a.y, a.z);
                ps[PF(u + 2)] = pack2(a.z, a.w);
                ps[PF(u + 3)] = pack2(a.w, nx);
            }
        }
    }
    __syncthreads();

    // ---- Phase 1: hh = g (x) q (81 taps); block 0 builds x~[0..95] ----
    if (tid < 81) {
        float q[18];
        q[0] = w_ar[0];
#pragma unroll
        for (int m = 1; m < 16; ++m) q[m] = w_ar[m] - w_ar[m - 1];
        q[16] = -1.f - w_ar[15];
        q[17] = 1.f;
        float h = 0.f;
#pragma unroll
        for (int m = 0; m < 18; ++m) {
            int k = tid - 17 + m;       // hh[i] = sum_k g[k] q[k+17-i]
            if (k >= 0 && k < 64) h = fmaf(q[m], garr[k], h);
        }
        hh2s[tid] = pack2(h, h);
    }
    if (bid == 0 && tid >= 160) {
        const int u = tid - 160;        // 0..95
        float v;
        if (u <= 16) {                  // x~ = y_u + sum_{j<=u} c_j y_{u-j}
            v = s[u + 1] - s[u];
            for (int j = 1; j <= u; ++j)
                v = fmaf(w_ma[16 - j], s[u - j + 1] - s[u - j], v);
        } else {                        // x = 18-tap q conv on s[u-16..u+1]
            float q[18];
            q[0] = w_ar[0];
#pragma unroll
            for (int m = 1; m < 16; ++m) q[m] = w_ar[m] - w_ar[m - 1];
            q[16] = -1.f - w_ar[15];
            q[17] = 1.f;
            v = 0.f;
#pragma unroll
            for (int m = 0; m < 18; ++m)
                v = fmaf(q[m], s[u - 16 + m], v);
        }
        xs[u] = v;
    }
    __syncthreads();

    // ---- Phase 2a: block 0 warp 0 — exact err for t in [0, 96) ----
    float accE = 0.f;
    if (bid == 0 && wid == 0) {
#pragma unroll
        for (int rr = 0; rr < 3; ++rr) {
            int t = l + 32 * rr;        // < 96
            float e = 0.f;
            int kmax = t < 63 ? t : 63;
            for (int k = 0; k <= kmax; ++k)
                e = fmaf(garr[k], xs[t - k], e);
            accE = fmaf(e, e, accE);
        }
    }

    // ---- Phase 2b: 81-tap packed conv, 32 outputs (16 pairs) per lane ----
    // Window invariant at tap T: W[(T+m)&31] = ps[tloc+1+T+m], m=0..31.
    // Pair p uses m = 2p; refill W[T&31] = ps[tloc+T+33].
    const int tloc = wid * 1024 + 32 * l;     // block-local first output
    ull E[16];
#pragma unroll
    for (int p = 0; p < 16; ++p) E[p] = 0ULL;
    ull W[32];
#pragma unroll
    for (int m = 0; m < 32; ++m) W[m] = ps[PF(tloc + 1 + m)];

#pragma unroll 1
    for (int o = 0; o < 2; ++o) {
        const int Tb = 32 * o;
#pragma unroll
        for (int k = 0; k < 32; ++k) {
            ull h2 = hh2s[80 - (Tb + k)];
#pragma unroll
            for (int p = 0; p < 16; ++p)
                E[p] = fma2(h2, W[(k + 2 * p) & 31], E[p]);
            W[k] = ps[PF(tloc + Tb + k + 33)];
        }
    }
#pragma unroll
    for (int k = 0; k < 16; ++k) {            // taps 64..79
        ull h2 = hh2s[16 - k];
#pragma unroll
        for (int p = 0; p < 16; ++p)
            E[p] = fma2(h2, W[(k + 2 * p) & 31], E[p]);
        W[k] = ps[PF(tloc + 64 + k + 33)];
    }
    {                                         // final tap T = 80
        ull h2 = hh2s[0];
#pragma unroll
        for (int p = 0; p < 16; ++p)
            E[p] = fma2(h2, W[(16 + 2 * p) & 31], E[p]);
    }

    ull acc2 = 0ULL;
    const bool skip = (gw == 0) & (l < 3);    // t < 96 handled exactly
    if (!skip) {
#pragma unroll
        for (int p = 0; p < 16; ++p)
            acc2 = fma2(E[p], E[p], acc2);
    }

    float alo, ahi;
    unpack2(acc2, alo, ahi);
    float acc = alo + ahi + accE;
#pragma unroll
    for (int off = 16; off; off >>= 1)
        acc += __shfl_down_sync(0xffffffffu, acc, off);
    if (l == 0) g_partial[gw] = acc;

    // ---- last-block-done final reduction ----
    __threadfence();
    __syncthreads();
    if (tid == 0) {
        unsigned old = atomicAdd(&g_cnt, 1u);
        s_done = (old == gridDim.x - 1) ? 1u : 0u;
    }
    __syncthreads();
    if (s_done) {
        double v = 0.0;
#pragma unroll
        for (int k = 0; k < NWARP / 256; ++k)
            v += (double)((volatile float*)g_partial)[tid + 256 * k];
#pragma unroll
        for (int off = 16; off; off >>= 1)
            v += __shfl_down_sync(0xffffffffu, v, off);
        if (l == 0) sm[wid] = v;
        __syncthreads();
        if (tid == 0) {
            double w = 0.0;
#pragma unroll
            for (int k = 0; k < WPB; ++k) w += sm[k];
            out[0] = (float)(w * (1.0 / (double)S_LEN));
            g_cnt = 0;                  // reset for next graph replay
        }
    }
}

extern "C" void kernel_launch(void* const* d_in, const int* in_sizes, int n_in,
                              void* d_out, int out_size) {
    const float* series = (const float*)d_in[0];
    const float* w_ar   = (const float*)d_in[1];
    const float* w_ma   = (const float*)d_in[2];
    float* out = (float*)d_out;
    cudaFuncSetAttribute(fused_kernel,
                         cudaFuncAttributeMaxDynamicSharedMemorySize,
                         PSALLOC * (int)sizeof(ull));
    fused_kernel<<<NBLK, 256, PSALLOC * sizeof(ull)>>>(series, w_ar, w_ma, out);
}